// round 2
// baseline (speedup 1.0000x reference)
#include <cuda_runtime.h>
#include <math.h>

#define Sq 2048
#define Ed 1024
#define NHh 4
#define HDd 256
#define Bb 2
#define BHh 8
#define E3 3072

#define TM 64
#define TN 64
#define QSTR 260   // padded row stride for Q/K/V tiles (floats)
#define PSTR 65    // padded row stride for P tile

// scratch (device globals: no allocations allowed)
__device__ float g_ig[BHh * Sq];
__device__ float g_fg[BHh * Sq];
__device__ float g_a[BHh * Sq];    // ig[j] - cs[j+1]
__device__ float g_pm[BHh * Sq];   // prefix max of a
__device__ float g_m[BHh * Sq];    // cs[j+1] + pm[j]  (stabilizer m)

// ---------------------------------------------------------------------------
// Kernel 1: gate projections. One block per (b,s); 8 warps = {i,f} x 4 heads.
// ---------------------------------------------------------------------------
__global__ void gates_kernel(const float* __restrict__ q,
                             const float* __restrict__ k,
                             const float* __restrict__ v,
                             const float* __restrict__ iw,
                             const float* __restrict__ ib,
                             const float* __restrict__ fw,
                             const float* __restrict__ fb) {
    __shared__ float gin[E3];
    int bs = blockIdx.x;
    int b = bs / Sq, s = bs % Sq;
    const float* qrow = q + (size_t)bs * Ed;
    const float* krow = k + (size_t)bs * Ed;
    const float* vrow = v + (size_t)bs * Ed;
    for (int i = threadIdx.x; i < Ed; i += blockDim.x) {
        gin[i]        = qrow[i];
        gin[Ed + i]   = krow[i];
        gin[2*Ed + i] = vrow[i];
    }
    __syncthreads();
    int w = threadIdx.x >> 5, lane = threadIdx.x & 31;
    int h = w & 3;
    const float* W = (w < 4) ? iw : fw;
    float sum = 0.f;
    #pragma unroll 4
    for (int r = lane; r < E3; r += 32) sum += gin[r] * W[r * NHh + h];
    #pragma unroll
    for (int off = 16; off; off >>= 1) sum += __shfl_down_sync(0xffffffffu, sum, off);
    if (lane == 0) {
        int idx = (b * NHh + h) * Sq + s;
        if (w < 4) g_ig[idx] = sum + ib[h];
        else       g_fg[idx] = sum + fb[h];
    }
}

// ---------------------------------------------------------------------------
// Kernel 2: per-head scans. cumsum(log_sigmoid(fg)) and prefix-max of
// a[j] = ig[j] - cs[j+1]. One block (1024 thr) per (b,h); 2 elems/thread.
// ---------------------------------------------------------------------------
__global__ void scan_kernel() {
    __shared__ float sv[Sq];     // log_f, then inclusive cumsum cs[j+1]
    __shared__ float av[Sq];     // a[j]
    __shared__ float part[1024];
    int bh = blockIdx.x;
    int t = threadIdx.x;
    const float* fgp = g_fg + bh * Sq;
    const float* igp = g_ig + bh * Sq;

    for (int e = t; e < Sq; e += 1024) {
        float x = fgp[e];
        // log_sigmoid, numerically stable both directions
        sv[e] = (x >= 0.f) ? -log1pf(expf(-x)) : (x - log1pf(expf(x)));
    }
    __syncthreads();

    // inclusive sum scan (pairwise + Hillis-Steele on 1024 partials)
    float p = sv[2*t] + sv[2*t + 1];
    part[t] = p;
    __syncthreads();
    for (int off = 1; off < 1024; off <<= 1) {
        float x = (t >= off) ? part[t - off] : 0.f;
        __syncthreads();
        part[t] += x;
        __syncthreads();
    }
    float base = (t > 0) ? part[t - 1] : 0.f;
    float cs0 = base + sv[2*t];
    float cs1 = cs0 + sv[2*t + 1];
    av[2*t]     = igp[2*t]     - cs0;
    av[2*t + 1] = igp[2*t + 1] - cs1;
    __syncthreads();

    // inclusive max scan of a[]
    part[t] = fmaxf(av[2*t], av[2*t + 1]);
    __syncthreads();
    for (int off = 1; off < 1024; off <<= 1) {
        float x = (t >= off) ? part[t - off] : -3.4e38f;
        __syncthreads();
        part[t] = fmaxf(part[t], x);
        __syncthreads();
    }
    float mbase = (t > 0) ? part[t - 1] : -3.4e38f;
    float pm0 = fmaxf(mbase, av[2*t]);
    float pm1 = fmaxf(pm0,  av[2*t + 1]);

    int o = bh * Sq + 2*t;
    g_a[o]      = av[2*t];
    g_a[o + 1]  = av[2*t + 1];
    g_pm[o]     = pm0;
    g_pm[o + 1] = pm1;
    g_m[o]      = cs0 + pm0;
    g_m[o + 1]  = cs1 + pm1;
}

// ---------------------------------------------------------------------------
// Kernel 3: main causal weighted attention + fused 1/(n+eps) + RMSNorm.
// Grid (32 row tiles [reversed for load balance], 8 bh). 256 threads.
// ---------------------------------------------------------------------------
__global__ void __launch_bounds__(256, 1)
attn_kernel(const float* __restrict__ q, const float* __restrict__ k,
            const float* __restrict__ v, const float* __restrict__ rms,
            float* __restrict__ out) {
    extern __shared__ float sm[];
    float* Qs   = sm;                     // 64 x QSTR
    float* Ks   = Qs + TM * QSTR;
    float* Vs   = Ks + TM * QSTR;
    float* Ps   = Vs + TM * QSTR;         // 64 x PSTR
    float* nrow = Ps + TM * PSTR;         // 64
    float* pmr  = nrow + TM;              // 64: prefmax for rows
    float* emr  = pmr + TM;               // 64: exp(-m) floor
    float* ajs  = emr + TM;               // 64: a[j] for current col tile

    int bh = blockIdx.y;
    int b = bh >> 2, h = bh & 3;
    int rt = gridDim.x - 1 - blockIdx.x;  // big tiles first
    int i0 = rt * TM;
    int t = threadIdx.x;
    int ty = t >> 4, tx = t & 15;

    // load Q tile (64 rows x 256 cols of this head)
    const float* qbase = q + ((size_t)b * Sq + i0) * Ed + h * HDd;
    for (int idx = t; idx < TM * 64; idx += 256) {
        int i = idx >> 6, c4 = (idx & 63) << 2;
        *(float4*)(Qs + i * QSTR + c4) = *(const float4*)(qbase + (size_t)i * Ed + c4);
    }
    if (t < TM) {
        nrow[t] = 0.f;
        pmr[t] = g_pm[bh * Sq + i0 + t];
        emr[t] = expf(-g_m[bh * Sq + i0 + t]);
    }

    float4 accO[4][4];  // [row r][col chunk ch] -> cols 64*ch + 4*tx
    #pragma unroll
    for (int r = 0; r < 4; r++)
        #pragma unroll
        for (int c = 0; c < 4; c++) accO[r][c] = make_float4(0.f, 0.f, 0.f, 0.f);

    for (int jt = 0; jt <= rt; jt++) {
        int j0 = jt * TM;
        __syncthreads();  // protect Ks/Vs/Ps from previous iteration readers
        const float* kbase = k + ((size_t)b * Sq + j0) * Ed + h * HDd;
        const float* vbase = v + ((size_t)b * Sq + j0) * Ed + h * HDd;
        for (int idx = t; idx < TM * 64; idx += 256) {
            int i = idx >> 6, c4 = (idx & 63) << 2;
            *(float4*)(Ks + i * QSTR + c4) = *(const float4*)(kbase + (size_t)i * Ed + c4);
            *(float4*)(Vs + i * QSTR + c4) = *(const float4*)(vbase + (size_t)i * Ed + c4);
        }
        if (t < TM) ajs[t] = g_a[bh * Sq + j0 + t];
        __syncthreads();

        // ---- scores: 4x4 micro-tile, rows 4*ty+r, cols tx+16*c ----
        float acc[4][4];
        #pragma unroll
        for (int r = 0; r < 4; r++)
            #pragma unroll
            for (int c = 0; c < 4; c++) acc[r][c] = 0.f;
        #pragma unroll 4
        for (int kk = 0; kk < HDd; kk += 4) {
            float4 qv[4], kv[4];
            #pragma unroll
            for (int r = 0; r < 4; r++)
                qv[r] = *(const float4*)(Qs + (4*ty + r) * QSTR + kk);
            #pragma unroll
            for (int c = 0; c < 4; c++)
                kv[c] = *(const float4*)(Ks + (tx + 16*c) * QSTR + kk);
            #pragma unroll
            for (int r = 0; r < 4; r++)
                #pragma unroll
                for (int c = 0; c < 4; c++)
                    acc[r][c] += qv[r].x*kv[c].x + qv[r].y*kv[c].y
                               + qv[r].z*kv[c].z + qv[r].w*kv[c].w;
        }
        bool diag = (jt == rt);
        #pragma unroll
        for (int r = 0; r < 4; r++) {
            int i = 4*ty + r;
            float pmv = pmr[i];
            #pragma unroll
            for (int c = 0; c < 4; c++) {
                int j = tx + 16*c;
                float val = 0.f;
                if (!diag || j <= i)
                    val = acc[r][c] * 0.0625f * expf(ajs[j] - pmv);
                Ps[i * PSTR + j] = val;
            }
        }
        __syncthreads();

        // row sums of P (denominator n)
        if (t < TM) {
            float s = 0.f;
            #pragma unroll 8
            for (int j = 0; j < TN; j++) s += Ps[t * PSTR + j];
            nrow[t] += s;
        }

        // ---- O += P @ V ----
        #pragma unroll 2
        for (int j = 0; j < TN; j++) {
            float pv[4];
            #pragma unroll
            for (int r = 0; r < 4; r++) pv[r] = Ps[(4*ty + r) * PSTR + j];
            #pragma unroll
            for (int ch = 0; ch < 4; ch++) {
                float4 vv = *(const float4*)(Vs + j * QSTR + 64*ch + 4*tx);
                #pragma unroll
                for (int r = 0; r < 4; r++) {
                    accO[r][ch].x += pv[r] * vv.x;
                    accO[r][ch].y += pv[r] * vv.y;
                    accO[r][ch].z += pv[r] * vv.z;
                    accO[r][ch].w += pv[r] * vv.w;
                }
            }
        }
    }
    __syncthreads();

    // ---- epilogue: 1/(n+eps), RMSNorm over HD, write out ----
    #pragma unroll
    for (int r = 0; r < 4; r++) {
        int i = 4*ty + r;
        float n = fmaxf(nrow[i], emr[i]) + 1e-6f;
        float inv = 1.f / n;
        float ssq = 0.f;
        #pragma unroll
        for (int ch = 0; ch < 4; ch++) {
            accO[r][ch].x *= inv; accO[r][ch].y *= inv;
            accO[r][ch].z *= inv; accO[r][ch].w *= inv;
            ssq += accO[r][ch].x * accO[r][ch].x + accO[r][ch].y * accO[r][ch].y
                 + accO[r][ch].z * accO[r][ch].z + accO[r][ch].w * accO[r][ch].w;
        }
        #pragma unroll
        for (int off = 8; off; off >>= 1)
            ssq += __shfl_xor_sync(0xffffffffu, ssq, off, 16);
        float rstd = rsqrtf(ssq * (1.f / 256.f) + 1e-6f);
        float* obase = out + ((size_t)b * Sq + i0 + i) * Ed + h * HDd;
        #pragma unroll
        for (int ch = 0; ch < 4; ch++) {
            float4 rs = *(const float4*)(rms + 64*ch + 4*tx);
            float4 o;
            o.x = accO[r][ch].x * rstd * (1.f + rs.x);
            o.y = accO[r][ch].y * rstd * (1.f + rs.y);
            o.z = accO[r][ch].z * rstd * (1.f + rs.z);
            o.w = accO[r][ch].w * rstd * (1.f + rs.w);
            *(float4*)(obase + 64*ch + 4*tx) = o;
        }
    }
}

// ---------------------------------------------------------------------------
extern "C" void kernel_launch(void* const* d_in, const int* in_sizes, int n_in,
                              void* d_out, int out_size) {
    (void)in_sizes; (void)n_in; (void)out_size;
    const float* q   = (const float*)d_in[0];
    const float* k   = (const float*)d_in[1];
    const float* v   = (const float*)d_in[2];
    const float* iw  = (const float*)d_in[3];
    const float* ib  = (const float*)d_in[4];
    const float* fw  = (const float*)d_in[5];
    const float* fb  = (const float*)d_in[6];
    const float* rms = (const float*)d_in[7];
    float* out = (float*)d_out;

    const int smem_bytes = (3 * TM * QSTR + TM * PSTR + 4 * TM) * (int)sizeof(float);
    cudaFuncSetAttribute(attn_kernel, cudaFuncAttributeMaxDynamicSharedMemorySize,
                         smem_bytes);

    gates_kernel<<<Bb * Sq, 256>>>(q, k, v, iw, ib, fw, fb);
    scan_kernel<<<BHh, 1024>>>();
    attn_kernel<<<dim3(Sq / TM, BHh), 256, smem_bytes>>>(q, k, v, rms, out);
}

// round 3
// speedup vs baseline: 2.1820x; 2.1820x over previous
#include <cuda_runtime.h>
#include <math.h>
#include <stdint.h>

#define Sq 2048
#define Ed 1024
#define NHh 4
#define HDd 256
#define Bb 2
#define BHh 8
#define E3 3072

#define TM 64
#define TN 64
#define QSTR 260   // 260 mod 32 == 4 -> conflict-free mma fragment LDS
#define PSTR 68    // 68 mod 32 == 4

#define FULLMASK 0xffffffffu

// scratch (device globals: no allocations allowed)
__device__ float g_ig[BHh * Sq];
__device__ float g_fg[BHh * Sq];
__device__ float g_a[BHh * Sq];      // a[j] = ig[j] - cs[j+1]
__device__ float g_pm[BHh * Sq];     // prefix max of a
__device__ float g_m[BHh * Sq];      // cs[j+1] + pm[j]
__device__ float g_ta[BHh * (Sq / TN)];  // per column tile max of a

// ---------------------------------------------------------------------------
// PTX helpers
// ---------------------------------------------------------------------------
__device__ __forceinline__ void mma8(float d[4], uint32_t a0, uint32_t a1,
                                     uint32_t a2, uint32_t a3,
                                     uint32_t b0, uint32_t b1) {
    asm volatile(
        "mma.sync.aligned.m16n8k8.row.col.f32.tf32.tf32.f32 "
        "{%0,%1,%2,%3}, {%4,%5,%6,%7}, {%8,%9}, {%0,%1,%2,%3};\n"
        : "+f"(d[0]), "+f"(d[1]), "+f"(d[2]), "+f"(d[3])
        : "r"(a0), "r"(a1), "r"(a2), "r"(a3), "r"(b0), "r"(b1));
}

__device__ __forceinline__ void cpa16(uint32_t dst, const void* src) {
    asm volatile("cp.async.cg.shared.global [%0], [%1], 16;\n"
                 :: "r"(dst), "l"(src));
}
#define CP_COMMIT() asm volatile("cp.async.commit_group;\n")
#define CP_WAIT(n)  asm volatile("cp.async.wait_group %0;\n" :: "n"(n))

// ---------------------------------------------------------------------------
// Kernel 1: gate projections. Block stages W (3072x8) in smem; one warp per
// (b,s) row; direct float4 global loads of q/k/v.
// ---------------------------------------------------------------------------
__global__ void __launch_bounds__(256, 1)
gates_kernel(const float* __restrict__ q, const float* __restrict__ k,
             const float* __restrict__ v, const float* __restrict__ iw,
             const float* __restrict__ ib, const float* __restrict__ fw,
             const float* __restrict__ fb) {
    extern __shared__ float sW[];  // [3072][8]: cols 0..3 = igate, 4..7 = fgate
    for (int i = threadIdx.x; i < E3; i += 256) {
        float4 wi = *(const float4*)(iw + i * 4);
        float4 wf = *(const float4*)(fw + i * 4);
        *(float4*)(sW + i * 8)     = wi;
        *(float4*)(sW + i * 8 + 4) = wf;
    }
    __syncthreads();

    int warp = threadIdx.x >> 5, lane = threadIdx.x & 31;
    int bs = blockIdx.x * 8 + warp;   // grid 512 -> 4096 rows
    const float* qrow = q + (size_t)bs * Ed;
    const float* krow = k + (size_t)bs * Ed;
    const float* vrow = v + (size_t)bs * Ed;

    float acc[8];
    #pragma unroll
    for (int j = 0; j < 8; j++) acc[j] = 0.f;

    #pragma unroll 2
    for (int it = 0; it < 8; it++) {
        int c4 = lane * 4 + it * 128;
        float4 xq = *(const float4*)(qrow + c4);
        float4 xk = *(const float4*)(krow + c4);
        float4 xv = *(const float4*)(vrow + c4);
        #pragma unroll
        for (int e = 0; e < 4; e++) {
            int r = c4 + e;
            float fq = (&xq.x)[e], fk = (&xk.x)[e], fv = (&xv.x)[e];
            float4 w0, w1;
            w0 = *(const float4*)(sW + (size_t)r * 8);
            w1 = *(const float4*)(sW + (size_t)r * 8 + 4);
            acc[0] += fq * w0.x; acc[1] += fq * w0.y; acc[2] += fq * w0.z; acc[3] += fq * w0.w;
            acc[4] += fq * w1.x; acc[5] += fq * w1.y; acc[6] += fq * w1.z; acc[7] += fq * w1.w;
            w0 = *(const float4*)(sW + (size_t)(Ed + r) * 8);
            w1 = *(const float4*)(sW + (size_t)(Ed + r) * 8 + 4);
            acc[0] += fk * w0.x; acc[1] += fk * w0.y; acc[2] += fk * w0.z; acc[3] += fk * w0.w;
            acc[4] += fk * w1.x; acc[5] += fk * w1.y; acc[6] += fk * w1.z; acc[7] += fk * w1.w;
            w0 = *(const float4*)(sW + (size_t)(2 * Ed + r) * 8);
            w1 = *(const float4*)(sW + (size_t)(2 * Ed + r) * 8 + 4);
            acc[0] += fv * w0.x; acc[1] += fv * w0.y; acc[2] += fv * w0.z; acc[3] += fv * w0.w;
            acc[4] += fv * w1.x; acc[5] += fv * w1.y; acc[6] += fv * w1.z; acc[7] += fv * w1.w;
        }
    }
    #pragma unroll
    for (int off = 16; off; off >>= 1)
        #pragma unroll
        for (int j = 0; j < 8; j++)
            acc[j] += __shfl_xor_sync(FULLMASK, acc[j], off);

    if (lane == 0) {
        int b = bs >> 11, s = bs & (Sq - 1);
        #pragma unroll
        for (int h = 0; h < NHh; h++) {
            int idx = (b * NHh + h) * Sq + s;
            g_ig[idx] = acc[h] + ib[h];
            g_fg[idx] = acc[4 + h] + fb[h];
        }
    }
}

// ---------------------------------------------------------------------------
// Kernel 2: per-head scans + per-tile max of a[].
// ---------------------------------------------------------------------------
__global__ void scan_kernel() {
    __shared__ float sv[Sq];
    __shared__ float av[Sq];
    __shared__ float part[1024];
    int bh = blockIdx.x;
    int t = threadIdx.x;
    const float* fgp = g_fg + bh * Sq;
    const float* igp = g_ig + bh * Sq;

    for (int e = t; e < Sq; e += 1024) {
        float x = fgp[e];
        sv[e] = (x >= 0.f) ? -log1pf(expf(-x)) : (x - log1pf(expf(x)));
    }
    __syncthreads();

    // inclusive sum scan
    float p = sv[2 * t] + sv[2 * t + 1];
    part[t] = p;
    __syncthreads();
    for (int off = 1; off < 1024; off <<= 1) {
        float x = (t >= off) ? part[t - off] : 0.f;
        __syncthreads();
        part[t] += x;
        __syncthreads();
    }
    float base = (t > 0) ? part[t - 1] : 0.f;
    float cs0 = base + sv[2 * t];
    float cs1 = cs0 + sv[2 * t + 1];
    av[2 * t]     = igp[2 * t]     - cs0;
    av[2 * t + 1] = igp[2 * t + 1] - cs1;
    __syncthreads();

    // per-64 tile maxes
    if (t < Sq / TN) {
        float mx = -3.4e38f;
        #pragma unroll 8
        for (int e = 0; e < TN; e++) mx = fmaxf(mx, av[t * TN + e]);
        g_ta[bh * (Sq / TN) + t] = mx;
    }

    // inclusive max scan
    part[t] = fmaxf(av[2 * t], av[2 * t + 1]);
    __syncthreads();
    for (int off = 1; off < 1024; off <<= 1) {
        float x = (t >= off) ? part[t - off] : -3.4e38f;
        __syncthreads();
        part[t] = fmaxf(part[t], x);
        __syncthreads();
    }
    float mbase = (t > 0) ? part[t - 1] : -3.4e38f;
    float pm0 = fmaxf(mbase, av[2 * t]);
    float pm1 = fmaxf(pm0, av[2 * t + 1]);

    int o = bh * Sq + 2 * t;
    g_a[o]      = av[2 * t];
    g_a[o + 1]  = av[2 * t + 1];
    g_pm[o]     = pm0;
    g_pm[o + 1] = pm1;
    g_m[o]      = cs0 + pm0;
    g_m[o + 1]  = cs1 + pm1;
}

// ---------------------------------------------------------------------------
// Kernel 3: tf32 tensor-core causal attention + fused 1/(n+eps) + RMSNorm.
// Grid (32 [reversed], 8 bh), 256 threads, 8 warps = 4 (row) x 2 (col).
// ---------------------------------------------------------------------------
__global__ void __launch_bounds__(256, 1)
attn_kernel(const float* __restrict__ q, const float* __restrict__ k,
            const float* __restrict__ v, const float* __restrict__ rms,
            float* __restrict__ out) {
    extern __shared__ float sm[];
    float* Qs    = sm;                    // 64 x QSTR
    float* Ks    = Qs + TM * QSTR;
    float* Vs    = Ks + TM * QSTR;
    float* Ps    = Vs + TM * QSTR;        // 64 x PSTR
    float* npart = Ps + TM * PSTR;        // [2][64] per-wc row-sum partials
    float* pmr   = npart + 128;           // 64
    float* emr   = pmr + 64;              // 64
    float* ejs   = emr + 64;              // 64
    float* rfac  = ejs + 64;              // 64
    float* ssqp  = rfac + 64;             // [2][64]

    const int KsO = TM * QSTR, VsO = 2 * TM * QSTR;
    uint32_t smBase = (uint32_t)__cvta_generic_to_shared(sm);

    int bh = blockIdx.y;
    int b = bh >> 2, h = bh & 3;
    int rt = gridDim.x - 1 - blockIdx.x;  // big row-tiles first
    int i0 = rt * TM;
    int t = threadIdx.x;
    int lane = t & 31, wid = t >> 5;
    int wr = wid & 3, wc = wid >> 2;
    int g = lane >> 2, c = lane & 3;

    // async load Q tile (group: Q)
    const float* qbase = q + ((size_t)(b * Sq + i0)) * Ed + h * HDd;
    for (int idx = t; idx < TM * 64; idx += 256) {
        int i = idx >> 6, c4 = (idx & 63) << 2;
        cpa16(smBase + (uint32_t)(i * QSTR + c4) * 4, qbase + (size_t)i * Ed + c4);
    }
    CP_COMMIT();

    if (t < 128) npart[t] = 0.f;
    if (t < TM) {
        pmr[t] = g_pm[bh * Sq + i0 + t];
        emr[t] = __expf(-g_m[bh * Sq + i0 + t]);
    }

    float accO[16][4];
    #pragma unroll
    for (int nt = 0; nt < 16; nt++)
        #pragma unroll
        for (int r = 0; r < 4; r++) accO[nt][r] = 0.f;

    const int iA = wr * 16 + g, iB = iA + 8;

    for (int jt = 0; jt <= rt; jt++) {
        int j0 = jt * TM;
        __syncthreads();  // prev-iter readers of Ks/Vs/Ps done

        const float* kb = k + ((size_t)(b * Sq + j0)) * Ed + h * HDd;
        const float* vb = v + ((size_t)(b * Sq + j0)) * Ed + h * HDd;
        for (int idx = t; idx < TM * 64; idx += 256) {
            int i = idx >> 6, c4 = (idx & 63) << 2;
            cpa16(smBase + (uint32_t)(KsO + i * QSTR + c4) * 4, kb + (size_t)i * Ed + c4);
        }
        CP_COMMIT();  // group: K
        for (int idx = t; idx < TM * 64; idx += 256) {
            int i = idx >> 6, c4 = (idx & 63) << 2;
            cpa16(smBase + (uint32_t)(VsO + i * QSTR + c4) * 4, vb + (size_t)i * Ed + c4);
        }
        CP_COMMIT();  // group: V

        float ta = g_ta[bh * (Sq / TN) + jt];
        if (t < TM) {
            ejs[t]  = __expf(g_a[bh * Sq + j0 + t] - ta);
            rfac[t] = __expf(ta - pmr[t]);
        }

        CP_WAIT(1);      // Q (first iter) + K arrived
        __syncthreads(); // K tile + ejs/rfac visible

        // ---- scores: warp computes rows [wr*16,+16) x cols [wc*32,+32) ----
        float acc[4][4];
        #pragma unroll
        for (int nt = 0; nt < 4; nt++)
            #pragma unroll
            for (int r = 0; r < 4; r++) acc[nt][r] = 0.f;

        const float* aR = Qs + (size_t)iA * QSTR + c;
        const float* bR = Ks + (size_t)(wc * 32 + g) * QSTR + c;
        #pragma unroll 4
        for (int kk = 0; kk < HDd; kk += 8) {
            uint32_t a0 = __float_as_uint(aR[kk]);
            uint32_t a1 = __float_as_uint(aR[8 * QSTR + kk]);
            uint32_t a2 = __float_as_uint(aR[kk + 4]);
            uint32_t a3 = __float_as_uint(aR[8 * QSTR + kk + 4]);
            #pragma unroll
            for (int nt = 0; nt < 4; nt++) {
                uint32_t b0 = __float_as_uint(bR[nt * 8 * QSTR + kk]);
                uint32_t b1 = __float_as_uint(bR[nt * 8 * QSTR + kk + 4]);
                mma8(acc[nt], a0, a1, a2, a3, b0, b1);
            }
        }

        // ---- apply decay factors, mask, store P, row sums ----
        bool diag = (jt == rt);
        float rA = rfac[iA] * 0.0625f;
        float rB = rfac[iB] * 0.0625f;
        float s0 = 0.f, s1 = 0.f;
        #pragma unroll
        for (int nt = 0; nt < 4; nt++) {
            int j = wc * 32 + nt * 8 + 2 * c;
            float e0 = ejs[j], e1 = ejs[j + 1];
            float p00 = acc[nt][0] * rA * e0;
            float p01 = acc[nt][1] * rA * e1;
            float p10 = acc[nt][2] * rB * e0;
            float p11 = acc[nt][3] * rB * e1;
            if (diag) {
                if (j > iA)     p00 = 0.f;
                if (j + 1 > iA) p01 = 0.f;
                if (j > iB)     p10 = 0.f;
                if (j + 1 > iB) p11 = 0.f;
            }
            Ps[iA * PSTR + j]     = p00;
            Ps[iA * PSTR + j + 1] = p01;
            Ps[iB * PSTR + j]     = p10;
            Ps[iB * PSTR + j + 1] = p11;
            s0 += p00 + p01;
            s1 += p10 + p11;
        }
        s0 += __shfl_xor_sync(FULLMASK, s0, 1);
        s0 += __shfl_xor_sync(FULLMASK, s0, 2);
        s1 += __shfl_xor_sync(FULLMASK, s1, 1);
        s1 += __shfl_xor_sync(FULLMASK, s1, 2);
        if (c == 0) {  // single writer per (wc,row): deterministic
            npart[wc * 64 + iA] += s0;
            npart[wc * 64 + iB] += s1;
        }

        CP_WAIT(0);      // V arrived
        __syncthreads(); // V + Ps visible

        // ---- O += P @ V : warp rows [wr*16,+16) x cols [wc*128,+128) ----
        const float* pA = Ps + (size_t)iA * PSTR + c;
        #pragma unroll
        for (int kk = 0; kk < TN; kk += 8) {
            uint32_t a0 = __float_as_uint(pA[kk]);
            uint32_t a1 = __float_as_uint(pA[8 * PSTR + kk]);
            uint32_t a2 = __float_as_uint(pA[kk + 4]);
            uint32_t a3 = __float_as_uint(pA[8 * PSTR + kk + 4]);
            const float* vR0 = Vs + (size_t)(kk + c) * QSTR + wc * 128 + g;
            const float* vR1 = vR0 + 4 * QSTR;
            #pragma unroll
            for (int nt = 0; nt < 16; nt++) {
                mma8(accO[nt], a0, a1, a2, a3,
                     __float_as_uint(vR0[nt * 8]),
                     __float_as_uint(vR1[nt * 8]));
            }
        }
    }
    __syncthreads();

    // ---- epilogue: 1/(n+eps), RMSNorm over HD=256, write out ----
    float nA = fmaxf(npart[iA] + npart[64 + iA], emr[iA]) + 1e-6f;
    float nB = fmaxf(npart[iB] + npart[64 + iB], emr[iB]) + 1e-6f;
    float invA = 1.f / nA, invB = 1.f / nB;
    float ssqA = 0.f, ssqB = 0.f;
    #pragma unroll
    for (int nt = 0; nt < 16; nt++) {
        accO[nt][0] *= invA; accO[nt][1] *= invA;
        accO[nt][2] *= invB; accO[nt][3] *= invB;
        ssqA += accO[nt][0] * accO[nt][0] + accO[nt][1] * accO[nt][1];
        ssqB += accO[nt][2] * accO[nt][2] + accO[nt][3] * accO[nt][3];
    }
    ssqA += __shfl_xor_sync(FULLMASK, ssqA, 1);
    ssqA += __shfl_xor_sync(FULLMASK, ssqA, 2);
    ssqB += __shfl_xor_sync(FULLMASK, ssqB, 1);
    ssqB += __shfl_xor_sync(FULLMASK, ssqB, 2);
    if (c == 0) {
        ssqp[wc * 64 + iA] = ssqA;
        ssqp[wc * 64 + iB] = ssqB;
    }
    __syncthreads();
    float rstdA = rsqrtf((ssqp[iA] + ssqp[64 + iA]) * (1.f / 256.f) + 1e-6f);
    float rstdB = rsqrtf((ssqp[iB] + ssqp[64 + iB]) * (1.f / 256.f) + 1e-6f);

    float* ob = out + ((size_t)(b * Sq + i0)) * Ed + h * HDd;
    #pragma unroll
    for (int nt = 0; nt < 16; nt++) {
        int col = wc * 128 + nt * 8 + 2 * c;
        float rs0 = rms[col], rs1 = rms[col + 1];
        float2 oA = make_float2(accO[nt][0] * rstdA * (1.f + rs0),
                                accO[nt][1] * rstdA * (1.f + rs1));
        float2 oB = make_float2(accO[nt][2] * rstdB * (1.f + rs0),
                                accO[nt][3] * rstdB * (1.f + rs1));
        *(float2*)(ob + (size_t)iA * Ed + col) = oA;
        *(float2*)(ob + (size_t)iB * Ed + col) = oB;
    }
}

// ---------------------------------------------------------------------------
extern "C" void kernel_launch(void* const* d_in, const int* in_sizes, int n_in,
                              void* d_out, int out_size) {
    (void)in_sizes; (void)n_in; (void)out_size;
    const float* q   = (const float*)d_in[0];
    const float* k   = (const float*)d_in[1];
    const float* v   = (const float*)d_in[2];
    const float* iw  = (const float*)d_in[3];
    const float* ib  = (const float*)d_in[4];
    const float* fw  = (const float*)d_in[5];
    const float* fb  = (const float*)d_in[6];
    const float* rms = (const float*)d_in[7];
    float* out = (float*)d_out;

    const int gates_smem = E3 * 8 * (int)sizeof(float);  // 96 KB
    const int attn_smem = (3 * TM * QSTR + TM * PSTR + 128 + 4 * 64 + 128)
                          * (int)sizeof(float);          // ~219 KB
    cudaFuncSetAttribute(gates_kernel,
                         cudaFuncAttributeMaxDynamicSharedMemorySize, gates_smem);
    cudaFuncSetAttribute(attn_kernel,
                         cudaFuncAttributeMaxDynamicSharedMemorySize, attn_smem);

    gates_kernel<<<Bb * Sq / 8, 256, gates_smem>>>(q, k, v, iw, ib, fw, fb);
    scan_kernel<<<BHh, 1024>>>();
    attn_kernel<<<dim3(Sq / TM, BHh), 256, attn_smem>>>(q, k, v, rms, out);
}

// round 8
// speedup vs baseline: 2.6375x; 1.2087x over previous
#include <cuda_runtime.h>
#include <cuda_fp16.h>
#include <math.h>
#include <stdint.h>

#define Sq 2048
#define Ed 1024
#define NHh 4
#define HDd 256
#define Bb 2
#define BHh 8
#define E3 3072

#define TM 64
#define TN 64
#define LDH 264      // half stride for Q/K tiles (528B: mod128=16 -> ldmatrix conflict-free)
#define VLD 72       // half stride for Vt tile (144B)
#define PLD 72       // half stride for P tile

#define FULLMASK 0xffffffffu

// ---------------- device-global scratch ----------------
__device__ float g_ig[BHh * Sq];
__device__ float g_fg[BHh * Sq];
__device__ float g_a[BHh * Sq];
__device__ float g_pm[BHh * Sq];
__device__ float g_m[BHh * Sq];
__device__ float g_ta[BHh * (Sq / TN)];
__device__ __half g_qh[(size_t)BHh * Sq * HDd];   // [b][h][s][d]
__device__ __half g_kh[(size_t)BHh * Sq * HDd];   // [b][h][s][d]
__device__ __half g_vt[(size_t)BHh * HDd * Sq];   // [b][h][d][s]

struct alignas(16) H8 { __half2 a, b, c, d; };

// ---------------- PTX helpers ----------------
__device__ __forceinline__ void mma16(float d[4], uint32_t a0, uint32_t a1,
                                      uint32_t a2, uint32_t a3,
                                      uint32_t b0, uint32_t b1) {
    asm volatile(
        "mma.sync.aligned.m16n8k16.row.col.f32.f16.f16.f32 "
        "{%0,%1,%2,%3}, {%4,%5,%6,%7}, {%8,%9}, {%0,%1,%2,%3};\n"
        : "+f"(d[0]), "+f"(d[1]), "+f"(d[2]), "+f"(d[3])
        : "r"(a0), "r"(a1), "r"(a2), "r"(a3), "r"(b0), "r"(b1));
}

__device__ __forceinline__ void ldsm4(uint32_t& r0, uint32_t& r1, uint32_t& r2,
                                      uint32_t& r3, uint32_t addr) {
    asm volatile("ldmatrix.sync.aligned.m8n8.x4.shared.b16 {%0,%1,%2,%3}, [%4];\n"
                 : "=r"(r0), "=r"(r1), "=r"(r2), "=r"(r3) : "r"(addr));
}

__device__ __forceinline__ void cpa16(uint32_t dst, const void* src) {
    asm volatile("cp.async.cg.shared.global [%0], [%1], 16;\n" :: "r"(dst), "l"(src));
}
#define CP_COMMIT() asm volatile("cp.async.commit_group;\n")
#define CP_WAIT(n)  asm volatile("cp.async.wait_group %0;\n" :: "n"(n))

// ---------------------------------------------------------------------------
// Kernel 1: gates + fp16 conversion of q,k into per-head layout.
// One block (128 thr) per (b,s) row. W read direct from global (L1/L2-hot).
// ---------------------------------------------------------------------------
__global__ void __launch_bounds__(128)
gates_kernel(const float* __restrict__ q, const float* __restrict__ k,
             const float* __restrict__ v, const float* __restrict__ iw,
             const float* __restrict__ ib, const float* __restrict__ fw,
             const float* __restrict__ fb) {
    __shared__ float red[4][8];
    int t = threadIdx.x;
    int bs = blockIdx.x;
    int b = bs >> 11, s = bs & (Sq - 1);
    int c0 = t * 8;

    const float* qrow = q + (size_t)bs * Ed;
    const float* krow = k + (size_t)bs * Ed;
    const float* vrow = v + (size_t)bs * Ed;

    float4 xq0 = *(const float4*)(qrow + c0);
    float4 xq1 = *(const float4*)(qrow + c0 + 4);
    float4 xk0 = *(const float4*)(krow + c0);
    float4 xk1 = *(const float4*)(krow + c0 + 4);
    float4 xv0 = *(const float4*)(vrow + c0);
    float4 xv1 = *(const float4*)(vrow + c0 + 4);

    // write q,k halves to per-head layout
    {
        int head = c0 >> 8, d = c0 & 255;
        size_t off = ((size_t)(b * NHh + head) * Sq + s) * HDd + d;
        H8 hq, hk;
        hq.a = __floats2half2_rn(xq0.x, xq0.y); hq.b = __floats2half2_rn(xq0.z, xq0.w);
        hq.c = __floats2half2_rn(xq1.x, xq1.y); hq.d = __floats2half2_rn(xq1.z, xq1.w);
        hk.a = __floats2half2_rn(xk0.x, xk0.y); hk.b = __floats2half2_rn(xk0.z, xk0.w);
        hk.c = __floats2half2_rn(xk1.x, xk1.y); hk.d = __floats2half2_rn(xk1.z, xk1.w);
        *(H8*)(g_qh + off) = hq;
        *(H8*)(g_kh + off) = hk;
    }

    float acc[8];
    #pragma unroll
    for (int j = 0; j < 8; j++) acc[j] = 0.f;

    float vals[3][8];
    #pragma unroll
    for (int e = 0; e < 4; e++) {
        vals[0][e] = (&xq0.x)[e]; vals[0][4 + e] = (&xq1.x)[e];
        vals[1][e] = (&xk0.x)[e]; vals[1][4 + e] = (&xk1.x)[e];
        vals[2][e] = (&xv0.x)[e]; vals[2][4 + e] = (&xv1.x)[e];
    }

    #pragma unroll
    for (int sec = 0; sec < 3; sec++) {
        #pragma unroll
        for (int e = 0; e < 8; e++) {
            int r = sec * Ed + c0 + e;
            float f = vals[sec][e];
            float4 wi = *(const float4*)(iw + (size_t)r * 4);
            float4 wf = *(const float4*)(fw + (size_t)r * 4);
            acc[0] += f * wi.x; acc[1] += f * wi.y; acc[2] += f * wi.z; acc[3] += f * wi.w;
            acc[4] += f * wf.x; acc[5] += f * wf.y; acc[6] += f * wf.z; acc[7] += f * wf.w;
        }
    }

    int lane = t & 31, w = t >> 5;
    #pragma unroll
    for (int off = 16; off; off >>= 1)
        #pragma unroll
        for (int j = 0; j < 8; j++)
            acc[j] += __shfl_xor_sync(FULLMASK, acc[j], off);
    if (lane == 0)
        #pragma unroll
        for (int j = 0; j < 8; j++) red[w][j] = acc[j];
    __syncthreads();
    if (t < 8) {
        float sum = red[0][t] + red[1][t] + red[2][t] + red[3][t];
        int h = t & 3;
        int idx = (b * NHh + h) * Sq + s;
        if (t < 4) g_ig[idx] = sum + ib[h];
        else       g_fg[idx] = sum + fb[h];
    }
}

// ---------------------------------------------------------------------------
// Kernel 1b: V transpose+convert -> g_vt[b][h][d][s]
// grid (Sq/64, BHh), 256 threads.
// ---------------------------------------------------------------------------
__global__ void __launch_bounds__(256)
vtrans_kernel(const float* __restrict__ v) {
    __shared__ __half sm[64 * LDH];
    int bh = blockIdx.y;
    int b = bh >> 2, h = bh & 3;
    int s0 = blockIdx.x * 64;
    int t = threadIdx.x;

    for (int idx = t; idx < 64 * 64; idx += 256) {
        int s = idx >> 6, d4 = (idx & 63) << 2;
        float4 x = *(const float4*)(v + ((size_t)(b * Sq + s0 + s)) * Ed + h * HDd + d4);
        __half2* dst = (__half2*)(sm + s * LDH + d4);
        dst[0] = __floats2half2_rn(x.x, x.y);
        dst[1] = __floats2half2_rn(x.z, x.w);
    }
    __syncthreads();

    int d = t;  // 0..255
    __half* orow = g_vt + ((size_t)bh * HDd + d) * Sq + s0;
    #pragma unroll
    for (int sc = 0; sc < 8; sc++) {
        H8 pk;
        __half tmp[8];
        #pragma unroll
        for (int e = 0; e < 8; e++) tmp[e] = sm[(sc * 8 + e) * LDH + d];
        pk.a = __halves2half2(tmp[0], tmp[1]);
        pk.b = __halves2half2(tmp[2], tmp[3]);
        pk.c = __halves2half2(tmp[4], tmp[5]);
        pk.d = __halves2half2(tmp[6], tmp[7]);
        *(H8*)(orow + sc * 8) = pk;
    }
}

// ---------------------------------------------------------------------------
// Kernel 2: per-head scans + per-tile max of a[].
// ---------------------------------------------------------------------------
__global__ void scan_kernel() {
    __shared__ float sv[Sq];
    __shared__ float av[Sq];
    __shared__ float part[1024];
    int bh = blockIdx.x;
    int t = threadIdx.x;
    const float* fgp = g_fg + bh * Sq;
    const float* igp = g_ig + bh * Sq;

    for (int e = t; e < Sq; e += 1024) {
        float x = fgp[e];
        sv[e] = (x >= 0.f) ? -log1pf(expf(-x)) : (x - log1pf(expf(x)));
    }
    __syncthreads();

    float p = sv[2 * t] + sv[2 * t + 1];
    part[t] = p;
    __syncthreads();
    for (int off = 1; off < 1024; off <<= 1) {
        float x = (t >= off) ? part[t - off] : 0.f;
        __syncthreads();
        part[t] += x;
        __syncthreads();
    }
    float base = (t > 0) ? part[t - 1] : 0.f;
    float cs0 = base + sv[2 * t];
    float cs1 = cs0 + sv[2 * t + 1];
    av[2 * t]     = igp[2 * t]     - cs0;
    av[2 * t + 1] = igp[2 * t + 1] - cs1;
    __syncthreads();

    if (t < Sq / TN) {
        float mx = -3.4e38f;
        #pragma unroll 8
        for (int e = 0; e < TN; e++) mx = fmaxf(mx, av[t * TN + e]);
        g_ta[bh * (Sq / TN) + t] = mx;
    }

    part[t] = fmaxf(av[2 * t], av[2 * t + 1]);
    __syncthreads();
    for (int off = 1; off < 1024; off <<= 1) {
        float x = (t >= off) ? part[t - off] : -3.4e38f;
        __syncthreads();
        part[t] = fmaxf(part[t], x);
        __syncthreads();
    }
    float mbase = (t > 0) ? part[t - 1] : -3.4e38f;
    float pm0 = fmaxf(mbase, av[2 * t]);
    float pm1 = fmaxf(pm0, av[2 * t + 1]);

    int o = bh * Sq + 2 * t;
    g_a[o]      = av[2 * t];
    g_a[o + 1]  = av[2 * t + 1];
    g_pm[o]     = pm0;
    g_pm[o + 1] = pm1;
    g_m[o]      = cs0 + pm0;
    g_m[o + 1]  = cs1 + pm1;
}

// ---------------------------------------------------------------------------
// Kernel 3: fp16 ldmatrix/mma attention + fused norm. 1D grid 256, 256 thr.
// ---------------------------------------------------------------------------
// smem map (halfs)
#define QS_OFF  0
#define KS_OFF  (TM * LDH)                 // 16896
#define KSZ     (TM * LDH)
#define VT_OFF  (KS_OFF + 2 * KSZ)         // 50688
#define VSZ     (HDd * VLD)                // 18432
#define PS_OFF  (VT_OFF + 2 * VSZ)         // 87552
#define HALF_TOT (PS_OFF + TM * PLD)       // 92160
#define FREG_BYTES (HALF_TOT * 2)          // 184320

__global__ void __launch_bounds__(256)
attn_kernel(const float* __restrict__ rms, float* __restrict__ out) {
    extern __shared__ __half smh[];
    float* fr    = (float*)((char*)smh + FREG_BYTES);
    float* npart = fr;          // 128
    float* pmr   = fr + 128;    // 64
    float* emr   = fr + 192;    // 64
    float* ejs   = fr + 256;    // 64
    float* rfac  = fr + 320;    // 64
    float* ssqp  = fr + 384;    // 128

    uint32_t smB = (uint32_t)__cvta_generic_to_shared(smh);

    int bx = blockIdx.x;
    int rt = (Sq / TM) - 1 - (bx >> 3);   // heavy tiles first, bh interleaved
    int bh = bx & 7;
    int b = bh >> 2, h = bh & 3;
    int i0 = rt * TM;
    int t = threadIdx.x;
    int lane = t & 31, wid = t >> 5;
    int wr = wid & 3, wc = wid >> 2;
    int g = lane >> 2, c = lane & 3;
    const int iA = wr * 16 + g, iB = iA + 8;

    const __half* qh = g_qh + (size_t)bh * Sq * HDd;
    const __half* kh = g_kh + (size_t)bh * Sq * HDd;
    const __half* vt = g_vt + (size_t)bh * HDd * Sq;

    // Q tile async load
    for (int idx = t; idx < TM * 32; idx += 256) {
        int i = idx >> 5, ch = (idx & 31) << 3;
        cpa16(smB + (uint32_t)(QS_OFF + i * LDH + ch) * 2,
              qh + (size_t)(i0 + i) * HDd + ch);
    }
    // K/V stage 0
    for (int idx = t; idx < TM * 32; idx += 256) {
        int i = idx >> 5, ch = (idx & 31) << 3;
        cpa16(smB + (uint32_t)(KS_OFF + i * LDH + ch) * 2,
              kh + (size_t)i * HDd + ch);
    }
    for (int idx = t; idx < HDd * 8; idx += 256) {
        int d = idx >> 3, ch = (idx & 7) << 3;
        cpa16(smB + (uint32_t)(VT_OFF + d * VLD + ch) * 2,
              vt + (size_t)d * Sq + ch);
    }
    CP_COMMIT();

    if (t < 128) npart[t] = 0.f;
    if (t < TM) {
        pmr[t] = g_pm[bh * Sq + i0 + t];
        emr[t] = __expf(-g_m[bh * Sq + i0 + t]);
    }

    float accO[16][4];
    #pragma unroll
    for (int nt = 0; nt < 16; nt++)
        #pragma unroll
        for (int r = 0; r < 4; r++) accO[nt][r] = 0.f;

    // per-lane ldmatrix row patterns
    const int rowPat = (lane & 7) + ((lane >> 3) & 1) * 8;   // A: row offset
    const int colPatA = (lane >> 4) * 8;                     // A: col offset
    const int rowPatB = (lane & 7) + ((lane >> 4) & 1) * 8;  // B: row offset
    const int colPatB = ((lane >> 3) & 1) * 8;               // B: col offset

    uint32_t aQaddr = smB + (uint32_t)(QS_OFF + (wr * 16 + rowPat) * LDH + colPatA) * 2;
    uint32_t aPaddr = smB + (uint32_t)(PS_OFF + (wr * 16 + rowPat) * PLD + colPatA) * 2;

    for (int jt = 0; jt <= rt; jt++) {
        int buf = jt & 1;
        int j0 = jt * TN;

        if (t < TM) {
            float ta = g_ta[bh * (Sq / TN) + jt];
            ejs[t]  = __expf(g_a[bh * Sq + j0 + t] - ta);
            rfac[t] = __expf(ta - pmr[t]);
        }

        CP_WAIT(0);
        __syncthreads();   // (a): stage[buf] ready; prev iter fully done

        if (jt < rt) {     // prefetch next stage into buf^1
            int nj0 = j0 + TN, nbuf = buf ^ 1;
            for (int idx = t; idx < TM * 32; idx += 256) {
                int i = idx >> 5, ch = (idx & 31) << 3;
                cpa16(smB + (uint32_t)(KS_OFF + nbuf * KSZ + i * LDH + ch) * 2,
                      kh + (size_t)(nj0 + i) * HDd + ch);
            }
            for (int idx = t; idx < HDd * 8; idx += 256) {
                int d = idx >> 3, ch = (idx & 7) << 3;
                cpa16(smB + (uint32_t)(VT_OFF + nbuf * VSZ + d * VLD + ch) * 2,
                      vt + (size_t)d * Sq + nj0 + ch);
            }
            CP_COMMIT();
        }

        // ---- QK^T: rows [wr*16,+16) x cols [wc*32,+32) ----
        float acc[4][4];
        #pragma unroll
        for (int nt = 0; nt < 4; nt++)
            #pragma unroll
            for (int r = 0; r < 4; r++) acc[nt][r] = 0.f;

        uint32_t bK0 = smB + (uint32_t)(KS_OFF + buf * KSZ
                          + (wc * 32 + rowPatB) * LDH + colPatB) * 2;
        uint32_t bK1 = bK0 + 16 * LDH * 2;
        #pragma unroll
        for (int kk = 0; kk < HDd; kk += 16) {
            uint32_t a0, a1, a2, a3, b00, b01, b10, b11, b20, b21, b30, b31;
            ldsm4(a0, a1, a2, a3, aQaddr + kk * 2);
            ldsm4(b00, b01, b10, b11, bK0 + kk * 2);
            ldsm4(b20, b21, b30, b31, bK1 + kk * 2);
            mma16(acc[0], a0, a1, a2, a3, b00, b01);
            mma16(acc[1], a0, a1, a2, a3, b10, b11);
            mma16(acc[2], a0, a1, a2, a3, b20, b21);
            mma16(acc[3], a0, a1, a2, a3, b30, b31);
        }

        // ---- scale, mask, store P (half), row sums ----
        bool diag = (jt == rt);
        float rA = rfac[iA] * 0.0625f;
        float rB = rfac[iB] * 0.0625f;
        float s0 = 0.f, s1 = 0.f;
        __half* Ps = smh + PS_OFF;
        #pragma unroll
        for (int nt = 0; nt < 4; nt++) {
            int j = wc * 32 + nt * 8 + 2 * c;
            float e0 = ejs[j], e1 = ejs[j + 1];
            float p00 = acc[nt][0] * rA * e0;
            float p01 = acc[nt][1] * rA * e1;
            float p10 = acc[nt][2] * rB * e0;
            float p11 = acc[nt][3] * rB * e1;
            if (diag) {
                if (j > iA)     p00 = 0.f;
                if (j + 1 > iA) p01 = 0.f;
                if (j > iB)     p10 = 0.f;
                if (j + 1 > iB) p11 = 0.f;
            }
            *(__half2*)(Ps + iA * PLD + j) = __floats2half2_rn(p00, p01);
            *(__half2*)(Ps + iB * PLD + j) = __floats2half2_rn(p10, p11);
            s0 += p00 + p01;
            s1 += p10 + p11;
        }
        s0 += __shfl_xor_sync(FULLMASK, s0, 1);
        s0 += __shfl_xor_sync(FULLMASK, s0, 2);
        s1 += __shfl_xor_sync(FULLMASK, s1, 1);
        s1 += __shfl_xor_sync(FULLMASK, s1, 2);
        if (c == 0) {
            npart[wc * 64 + iA] += s0;
            npart[wc * 64 + iB] += s1;
        }

        __syncthreads();   // (b): P visible

        // ---- O += P @ V : rows [wr*16,+16) x d-cols [wc*128,+128) ----
        uint32_t vBase = smB + (uint32_t)(VT_OFF + buf * VSZ
                           + (wc * 128 + rowPatB) * VLD + colPatB) * 2;
        #pragma unroll
        for (int kk = 0; kk < TN; kk += 16) {
            uint32_t a0, a1, a2, a3;
            ldsm4(a0, a1, a2, a3, aPaddr + kk * 2);
            #pragma unroll
            for (int nb = 0; nb < 8; nb++) {
                uint32_t b0, b1, b2, b3;
                ldsm4(b0, b1, b2, b3, vBase + (uint32_t)(nb * 16 * VLD + kk) * 2);
                mma16(accO[nb * 2],     a0, a1, a2, a3, b0, b1);
                mma16(accO[nb * 2 + 1], a0, a1, a2, a3, b2, b3);
            }
        }
    }
    __syncthreads();

    // ---- epilogue ----
    float nA = fmaxf(npart[iA] + npart[64 + iA], emr[iA]) + 1e-6f;
    float nB = fmaxf(npart[iB] + npart[64 + iB], emr[iB]) + 1e-6f;
    float invA = 1.f / nA, invB = 1.f / nB;
    float ssqA = 0.f, ssqB = 0.f;
    #pragma unroll
    for (int nt = 0; nt < 16; nt++) {
        accO[nt][0] *= invA; accO[nt][1] *= invA;
        accO[nt][2] *= invB; accO[nt][3] *= invB;
        ssqA += accO[nt][0] * accO[nt][0] + accO[nt][1] * accO[nt][1];
        ssqB += accO[nt][2] * accO[nt][2] + accO[nt][3] * accO[nt][3];
    }
    ssqA += __shfl_xor_sync(FULLMASK, ssqA, 1);
    ssqA += __shfl_xor_sync(FULLMASK, ssqA, 2);
    ssqB += __shfl_xor_sync(FULLMASK, ssqB, 1);
    ssqB += __shfl_xor_sync(FULLMASK, ssqB, 2);
    if (c == 0) {
        ssqp[wc * 64 + iA] = ssqA;
        ssqp[wc * 64 + iB] = ssqB;
    }
    __syncthreads();
    float rstdA = rsqrtf((ssqp[iA] + ssqp[64 + iA]) * (1.f / 256.f) + 1e-6f);
    float rstdB = rsqrtf((ssqp[iB] + ssqp[64 + iB]) * (1.f / 256.f) + 1e-6f);

    float* ob = out + ((size_t)(b * Sq + i0)) * Ed + h * HDd;
    #pragma unroll
    for (int nt = 0; nt < 16; nt++) {
        int col = wc * 128 + nt * 8 + 2 * c;
        float rs0 = rms[col], rs1 = rms[col + 1];
        *(float2*)(ob + (size_t)iA * Ed + col) =
            make_float2(accO[nt][0] * rstdA * (1.f + rs0),
                        accO[nt][1] * rstdA * (1.f + rs1));
        *(float2*)(ob + (size_t)iB * Ed + col) =
            make_float2(accO[nt][2] * rstdB * (1.f + rs0),
                        accO[nt][3] * rstdB * (1.f + rs1));
    }
}

// ---------------------------------------------------------------------------
extern "C" void kernel_launch(void* const* d_in, const int* in_sizes, int n_in,
                              void* d_out, int out_size) {
    (void)in_sizes; (void)n_in; (void)out_size;
    const float* q   = (const float*)d_in[0];
    const float* k   = (const float*)d_in[1];
    const float* v   = (const float*)d_in[2];
    const float* iw  = (const float*)d_in[3];
    const float* ib  = (const float*)d_in[4];
    const float* fw  = (const float*)d_in[5];
    const float* fb  = (const float*)d_in[6];
    const float* rms = (const float*)d_in[7];
    float* out = (float*)d_out;

    const int attn_smem = FREG_BYTES + 512 * 4;   // 186368 B
    cudaFuncSetAttribute(attn_kernel,
                         cudaFuncAttributeMaxDynamicSharedMemorySize, attn_smem);

    gates_kernel<<<Bb * Sq, 128>>>(q, k, v, iw, ib, fw, fb);
    vtrans_kernel<<<dim3(Sq / 64, BHh), 256>>>(v);
    scan_kernel<<<BHh, 1024>>>();
    attn_kernel<<<(Sq / TM) * BHh, 256, attn_smem>>>(rms, out);
}

// round 9
// speedup vs baseline: 5.5777x; 2.1148x over previous
#include <cuda_runtime.h>
#include <cuda_fp16.h>
#include <math.h>
#include <stdint.h>

#define Sq 2048
#define Ed 1024
#define NHh 4
#define HDd 256
#define Bb 2
#define BHh 8
#define E3 3072

#define TM 64
#define TN 64
#define LDH 264      // half stride for Q/K/V tiles (528B: mod128=16 -> ldmatrix conflict-free)
#define PLD 72       // half stride for P tile

#define FULLMASK 0xffffffffu

// ---------------- device-global scratch ----------------
__device__ float g_ig[BHh * Sq];
__device__ float g_fg[BHh * Sq];
__device__ float g_a[BHh * Sq];
__device__ float g_pm[BHh * Sq];
__device__ float g_m[BHh * Sq];
__device__ float g_ta[BHh * (Sq / TN)];
__device__ __half g_qh[(size_t)BHh * Sq * HDd];   // [b][h][s][d]
__device__ __half g_kh[(size_t)BHh * Sq * HDd];   // [b][h][s][d]
__device__ __half g_vh[(size_t)BHh * Sq * HDd];   // [b][h][s][d]

struct alignas(8) H4 { __half2 a, b; };

// ---------------- PTX helpers ----------------
__device__ __forceinline__ void mma16(float d[4], uint32_t a0, uint32_t a1,
                                      uint32_t a2, uint32_t a3,
                                      uint32_t b0, uint32_t b1) {
    asm volatile(
        "mma.sync.aligned.m16n8k16.row.col.f32.f16.f16.f32 "
        "{%0,%1,%2,%3}, {%4,%5,%6,%7}, {%8,%9}, {%0,%1,%2,%3};\n"
        : "+f"(d[0]), "+f"(d[1]), "+f"(d[2]), "+f"(d[3])
        : "r"(a0), "r"(a1), "r"(a2), "r"(a3), "r"(b0), "r"(b1));
}

__device__ __forceinline__ void ldsm4(uint32_t& r0, uint32_t& r1, uint32_t& r2,
                                      uint32_t& r3, uint32_t addr) {
    asm volatile("ldmatrix.sync.aligned.m8n8.x4.shared.b16 {%0,%1,%2,%3}, [%4];\n"
                 : "=r"(r0), "=r"(r1), "=r"(r2), "=r"(r3) : "r"(addr));
}

__device__ __forceinline__ void ldsm4t(uint32_t& r0, uint32_t& r1, uint32_t& r2,
                                       uint32_t& r3, uint32_t addr) {
    asm volatile("ldmatrix.sync.aligned.m8n8.x4.trans.shared.b16 {%0,%1,%2,%3}, [%4];\n"
                 : "=r"(r0), "=r"(r1), "=r"(r2), "=r"(r3) : "r"(addr));
}

__device__ __forceinline__ void cpa16(uint32_t dst, const void* src) {
    asm volatile("cp.async.cg.shared.global [%0], [%1], 16;\n" :: "r"(dst), "l"(src));
}
#define CP_COMMIT() asm volatile("cp.async.commit_group;\n")
#define CP_WAIT(n)  asm volatile("cp.async.wait_group %0;\n" :: "n"(n))

// ---------------------------------------------------------------------------
// Kernel 1: gates + fp16 conversion of q,k,v into per-head layout.
// 128 blocks x 256 thr. W transposed in smem: sWT[j][3072] -> conflict-free
// float4 LDS at word offset 4*lane. Each warp handles 4 rows sequentially.
// ---------------------------------------------------------------------------
__global__ void __launch_bounds__(256)
gates_kernel(const float* __restrict__ q, const float* __restrict__ k,
             const float* __restrict__ v, const float* __restrict__ iw,
             const float* __restrict__ ib, const float* __restrict__ fw,
             const float* __restrict__ fb) {
    extern __shared__ float sWT[];   // [8][3072] = 96 KB
    int t = threadIdx.x;
    int lane = t & 31, warp = t >> 5;

    // stage W transposed (conflict-free STS: word = r mod 32 distinct per lane)
    for (int r = t; r < E3; r += 256) {
        float4 wi = *(const float4*)(iw + (size_t)r * 4);
        float4 wf = *(const float4*)(fw + (size_t)r * 4);
        sWT[0 * E3 + r] = wi.x; sWT[1 * E3 + r] = wi.y;
        sWT[2 * E3 + r] = wi.z; sWT[3 * E3 + r] = wi.w;
        sWT[4 * E3 + r] = wf.x; sWT[5 * E3 + r] = wf.y;
        sWT[6 * E3 + r] = wf.z; sWT[7 * E3 + r] = wf.w;
    }
    __syncthreads();

    #pragma unroll 1
    for (int rr = 0; rr < 4; rr++) {
        int bs = blockIdx.x * 32 + warp * 4 + rr;
        int b = bs >> 11, s = bs & (Sq - 1);
        const float* qrow = q + (size_t)bs * Ed;
        const float* krow = k + (size_t)bs * Ed;
        const float* vrow = v + (size_t)bs * Ed;

        float acc[8];
        #pragma unroll
        for (int j = 0; j < 8; j++) acc[j] = 0.f;

        #pragma unroll 1
        for (int i = 0; i < 24; i++) {
            int sec = i >> 3;                    // 0:q 1:k 2:v
            int fs = lane + 32 * (i & 7);        // float4 idx within section
            const float* src = (sec == 0) ? qrow : (sec == 1) ? krow : vrow;
            float4 x = *(const float4*)(src + (size_t)fs * 4);
            int rg = sec * Ed + fs * 4;          // global W row of x.x
            #pragma unroll
            for (int j = 0; j < 8; j++) {
                float4 wj = *(const float4*)(sWT + j * E3 + rg);
                acc[j] += x.x * wj.x + x.y * wj.y + x.z * wj.z + x.w * wj.w;
            }
            // fp16 conversion, coalesced 8B store
            int rf = fs * 4;                     // 0..1023 within section
            int head = rf >> 8, d = rf & 255;
            size_t off = ((size_t)(b * NHh + head) * Sq + s) * HDd + d;
            H4 hx;
            hx.a = __floats2half2_rn(x.x, x.y);
            hx.b = __floats2half2_rn(x.z, x.w);
            __half* dst = (sec == 0) ? g_qh : (sec == 1) ? g_kh : g_vh;
            *(H4*)(dst + off) = hx;
        }

        #pragma unroll
        for (int off = 16; off; off >>= 1)
            #pragma unroll
            for (int j = 0; j < 8; j++)
                acc[j] += __shfl_xor_sync(FULLMASK, acc[j], off);
        if (lane == 0) {
            #pragma unroll
            for (int h = 0; h < NHh; h++) {
                int idx = (b * NHh + h) * Sq + s;
                g_ig[idx] = acc[h] + ib[h];
                g_fg[idx] = acc[4 + h] + fb[h];
            }
        }
    }
}

// ---------------------------------------------------------------------------
// Kernel 2: per-head scans + per-tile max of a[].
// ---------------------------------------------------------------------------
__global__ void scan_kernel() {
    __shared__ float sv[Sq];
    __shared__ float av[Sq];
    __shared__ float part[1024];
    int bh = blockIdx.x;
    int t = threadIdx.x;
    const float* fgp = g_fg + bh * Sq;
    const float* igp = g_ig + bh * Sq;

    for (int e = t; e < Sq; e += 1024) {
        float x = fgp[e];
        sv[e] = (x >= 0.f) ? -log1pf(expf(-x)) : (x - log1pf(expf(x)));
    }
    __syncthreads();

    float p = sv[2 * t] + sv[2 * t + 1];
    part[t] = p;
    __syncthreads();
    for (int off = 1; off < 1024; off <<= 1) {
        float x = (t >= off) ? part[t - off] : 0.f;
        __syncthreads();
        part[t] += x;
        __syncthreads();
    }
    float base = (t > 0) ? part[t - 1] : 0.f;
    float cs0 = base + sv[2 * t];
    float cs1 = cs0 + sv[2 * t + 1];
    av[2 * t]     = igp[2 * t]     - cs0;
    av[2 * t + 1] = igp[2 * t + 1] - cs1;
    __syncthreads();

    if (t < Sq / TN) {
        float mx = -3.4e38f;
        #pragma unroll 8
        for (int e = 0; e < TN; e++) mx = fmaxf(mx, av[t * TN + e]);
        g_ta[bh * (Sq / TN) + t] = mx;
    }

    part[t] = fmaxf(av[2 * t], av[2 * t + 1]);
    __syncthreads();
    for (int off = 1; off < 1024; off <<= 1) {
        float x = (t >= off) ? part[t - off] : -3.4e38f;
        __syncthreads();
        part[t] = fmaxf(part[t], x);
        __syncthreads();
    }
    float mbase = (t > 0) ? part[t - 1] : -3.4e38f;
    float pm0 = fmaxf(mbase, av[2 * t]);
    float pm1 = fmaxf(pm0, av[2 * t + 1]);

    int o = bh * Sq + 2 * t;
    g_a[o]      = av[2 * t];
    g_a[o + 1]  = av[2 * t + 1];
    g_pm[o]     = pm0;
    g_pm[o + 1] = pm1;
    g_m[o]      = cs0 + pm0;
    g_m[o + 1]  = cs1 + pm1;
}

// ---------------------------------------------------------------------------
// Kernel 3: fp16 attention, balanced pairing: 128 blocks (single wave),
// block (pr,bh) processes row tiles {31-pr, pr} -> exactly 33 col-iters each.
// V is [s][d]; PV B-fragments via ldmatrix.trans.
// ---------------------------------------------------------------------------
// smem map (halfs)
#define QS_OFF  0
#define TSZ     (TM * LDH)                 // 16896 halves per tile
#define KS_OFF  TSZ
#define VS_OFF  (KS_OFF + 2 * TSZ)
#define PS_OFF  (VS_OFF + 2 * TSZ)
#define HALF_TOT (PS_OFF + TM * PLD)       // 89088
#define FREG_BYTES (HALF_TOT * 2)          // 178176

__global__ void __launch_bounds__(256)
attn_kernel(const float* __restrict__ rms, float* __restrict__ out) {
    extern __shared__ __half smh[];
    float* fr    = (float*)((char*)smh + FREG_BYTES);
    float* npart = fr;          // 128
    float* pmr   = fr + 128;    // 64
    float* emr   = fr + 192;    // 64
    float* ejs   = fr + 256;    // 64
    float* rfac  = fr + 320;    // 64
    float* ssqp  = fr + 384;    // 128

    uint32_t smB = (uint32_t)__cvta_generic_to_shared(smh);

    int pr = blockIdx.x >> 3;             // 0..15
    int bh = blockIdx.x & 7;
    int b = bh >> 2, h = bh & 3;
    int t = threadIdx.x;
    int lane = t & 31, wid = t >> 5;
    int wr = wid & 3, wc = wid >> 2;
    int g = lane >> 2, c = lane & 3;
    const int iA = wr * 16 + g, iB = iA + 8;

    const __half* qh = g_qh + (size_t)bh * Sq * HDd;
    const __half* kh = g_kh + (size_t)bh * Sq * HDd;
    const __half* vh = g_vh + (size_t)bh * Sq * HDd;

    // per-lane ldmatrix patterns
    const int rowPat  = (lane & 7) + ((lane >> 3) & 1) * 8;   // A rows
    const int colPatA = (lane >> 4) * 8;                      // A cols
    const int rowPatB = (lane & 7) + ((lane >> 4) & 1) * 8;   // K-B rows (non-trans)
    const int colPatB = ((lane >> 3) & 1) * 8;                // K-B cols
    const int vRowL   = lane & 15;                            // V-B rows (trans)
    const int vColL   = wc * 128 + ((lane >> 4) & 1) * 8;     // V-B col base

    uint32_t aQaddr = smB + (uint32_t)(QS_OFF + (wr * 16 + rowPat) * LDH + colPatA) * 2;
    uint32_t aPaddr = smB + (uint32_t)(PS_OFF + (wr * 16 + rowPat) * PLD + colPatA) * 2;

    #pragma unroll 1
    for (int tile = 0; tile < 2; tile++) {
        int rt = tile ? pr : (Sq / TM - 1 - pr);   // heavy tile first
        int i0 = rt * TM;

        __syncthreads();   // smem safe to reinit (prev tile's readers done)

        // Q tile + K/V stage 0 (one cp.async group)
        for (int idx = t; idx < TM * 32; idx += 256) {
            int i = idx >> 5, ch = (idx & 31) << 3;
            cpa16(smB + (uint32_t)(QS_OFF + i * LDH + ch) * 2,
                  qh + (size_t)(i0 + i) * HDd + ch);
            cpa16(smB + (uint32_t)(KS_OFF + i * LDH + ch) * 2,
                  kh + (size_t)i * HDd + ch);
            cpa16(smB + (uint32_t)(VS_OFF + i * LDH + ch) * 2,
                  vh + (size_t)i * HDd + ch);
        }
        CP_COMMIT();

        if (t < 128) npart[t] = 0.f;
        if (t < TM) {
            pmr[t] = g_pm[bh * Sq + i0 + t];
            emr[t] = __expf(-g_m[bh * Sq + i0 + t]);
        }

        float accO[16][4];
        #pragma unroll
        for (int nt = 0; nt < 16; nt++)
            #pragma unroll
            for (int r = 0; r < 4; r++) accO[nt][r] = 0.f;

        #pragma unroll 1
        for (int jt = 0; jt <= rt; jt++) {
            int buf = jt & 1;
            int j0 = jt * TN;

            if (t < TM) {
                float ta = g_ta[bh * (Sq / TN) + jt];
                ejs[t]  = __expf(g_a[bh * Sq + j0 + t] - ta);
                rfac[t] = __expf(ta - pmr[t]);
            }

            CP_WAIT(0);
            __syncthreads();   // stage[buf] + ejs/rfac ready; prev readers done

            if (jt < rt) {     // prefetch next stage
                int nj0 = j0 + TN, nbuf = buf ^ 1;
                for (int idx = t; idx < TM * 32; idx += 256) {
                    int i = idx >> 5, ch = (idx & 31) << 3;
                    cpa16(smB + (uint32_t)(KS_OFF + nbuf * TSZ + i * LDH + ch) * 2,
                          kh + (size_t)(nj0 + i) * HDd + ch);
                    cpa16(smB + (uint32_t)(VS_OFF + nbuf * TSZ + i * LDH + ch) * 2,
                          vh + (size_t)(nj0 + i) * HDd + ch);
                }
                CP_COMMIT();
            }

            // ---- QK^T: rows [wr*16,+16) x cols [wc*32,+32) ----
            float acc[4][4];
            #pragma unroll
            for (int nt = 0; nt < 4; nt++)
                #pragma unroll
                for (int r = 0; r < 4; r++) acc[nt][r] = 0.f;

            uint32_t bK0 = smB + (uint32_t)(KS_OFF + buf * TSZ
                              + (wc * 32 + rowPatB) * LDH + colPatB) * 2;
            uint32_t bK1 = bK0 + 16 * LDH * 2;
            #pragma unroll
            for (int kk = 0; kk < HDd; kk += 16) {
                uint32_t a0, a1, a2, a3, b00, b01, b10, b11, b20, b21, b30, b31;
                ldsm4(a0, a1, a2, a3, aQaddr + kk * 2);
                ldsm4(b00, b01, b10, b11, bK0 + kk * 2);
                ldsm4(b20, b21, b30, b31, bK1 + kk * 2);
                mma16(acc[0], a0, a1, a2, a3, b00, b01);
                mma16(acc[1], a0, a1, a2, a3, b10, b11);
                mma16(acc[2], a0, a1, a2, a3, b20, b21);
                mma16(acc[3], a0, a1, a2, a3, b30, b31);
            }

            // ---- scale, mask, store P (half), row sums ----
            bool diag = (jt == rt);
            float rA = rfac[iA] * 0.0625f;
            float rB = rfac[iB] * 0.0625f;
            float s0 = 0.f, s1 = 0.f;
            __half* Ps = smh + PS_OFF;
            #pragma unroll
            for (int nt = 0; nt < 4; nt++) {
                int j = wc * 32 + nt * 8 + 2 * c;
                float e0 = ejs[j], e1 = ejs[j + 1];
                float p00 = acc[nt][0] * rA * e0;
                float p01 = acc[nt][1] * rA * e1;
                float p10 = acc[nt][2] * rB * e0;
                float p11 = acc[nt][3] * rB * e1;
                if (diag) {
                    if (j > iA)     p00 = 0.f;
                    if (j + 1 > iA) p01 = 0.f;
                    if (j > iB)     p10 = 0.f;
                    if (j + 1 > iB) p11 = 0.f;
                }
                *(__half2*)(Ps + iA * PLD + j) = __floats2half2_rn(p00, p01);
                *(__half2*)(Ps + iB * PLD + j) = __floats2half2_rn(p10, p11);
                s0 += p00 + p01;
                s1 += p10 + p11;
            }
            s0 += __shfl_xor_sync(FULLMASK, s0, 1);
            s0 += __shfl_xor_sync(FULLMASK, s0, 2);
            s1 += __shfl_xor_sync(FULLMASK, s1, 1);
            s1 += __shfl_xor_sync(FULLMASK, s1, 2);
            if (c == 0) {
                npart[wc * 64 + iA] += s0;
                npart[wc * 64 + iB] += s1;
            }

            __syncthreads();   // P visible

            // ---- O += P @ V : rows [wr*16,+16) x d-cols [wc*128,+128) ----
            uint32_t vB = smB + (uint32_t)(VS_OFF + buf * TSZ + vRowL * LDH + vColL) * 2;
            #pragma unroll
            for (int kk = 0; kk < TN; kk += 16) {
                uint32_t a0, a1, a2, a3;
                ldsm4(a0, a1, a2, a3, aPaddr + kk * 2);
                uint32_t vRow = vB + (uint32_t)(kk * LDH) * 2;
                #pragma unroll
                for (int nb = 0; nb < 8; nb++) {
                    uint32_t b0, b1, b2, b3;
                    ldsm4t(b0, b1, b2, b3, vRow + (uint32_t)(nb * 16) * 2);
                    mma16(accO[nb * 2],     a0, a1, a2, a3, b0, b1);
                    mma16(accO[nb * 2 + 1], a0, a1, a2, a3, b2, b3);
                }
            }
        }
        __syncthreads();

        // ---- epilogue: 1/(n+eps), RMSNorm over HD=256, write out ----
        float nA = fmaxf(npart[iA] + npart[64 + iA], emr[iA]) + 1e-6f;
        float nB = fmaxf(npart[iB] + npart[64 + iB], emr[iB]) + 1e-6f;
        float invA = 1.f / nA, invB = 1.f / nB;
        float ssqA = 0.f, ssqB = 0.f;
        #pragma unroll
        for (int nt = 0; nt < 16; nt++) {
            accO[nt][0] *= invA; accO[nt][1] *= invA;
            accO[nt][2] *= invB; accO[nt][3] *= invB;
            ssqA += accO[nt][0] * accO[nt][0] + accO[nt][1] * accO[nt][1];
            ssqB += accO[nt][2] * accO[nt][2] + accO[nt][3] * accO[nt][3];
        }
        ssqA += __shfl_xor_sync(FULLMASK, ssqA, 1);
        ssqA += __shfl_xor_sync(FULLMASK, ssqA, 2);
        ssqB += __shfl_xor_sync(FULLMASK, ssqB, 1);
        ssqB += __shfl_xor_sync(FULLMASK, ssqB, 2);
        if (c == 0) {
            ssqp[wc * 64 + iA] = ssqA;
            ssqp[wc * 64 + iB] = ssqB;
        }
        __syncthreads();
        float rstdA = rsqrtf((ssqp[iA] + ssqp[64 + iA]) * (1.f / 256.f) + 1e-6f);
        float rstdB = rsqrtf((ssqp[iB] + ssqp[64 + iB]) * (1.f / 256.f) + 1e-6f);

        float* ob = out + ((size_t)(b * Sq + i0)) * Ed + h * HDd;
        #pragma unroll
        for (int nt = 0; nt < 16; nt++) {
            int col = wc * 128 + nt * 8 + 2 * c;
            float rs0 = rms[col], rs1 = rms[col + 1];
            *(float2*)(ob + (size_t)iA * Ed + col) =
                make_float2(accO[nt][0] * rstdA * (1.f + rs0),
                            accO[nt][1] * rstdA * (1.f + rs1));
            *(float2*)(ob + (size_t)iB * Ed + col) =
                make_float2(accO[nt][2] * rstdB * (1.f + rs0),
                            accO[nt][3] * rstdB * (1.f + rs1));
        }
    }
}

// ---------------------------------------------------------------------------
extern "C" void kernel_launch(void* const* d_in, const int* in_sizes, int n_in,
                              void* d_out, int out_size) {
    (void)in_sizes; (void)n_in; (void)out_size;
    const float* q   = (const float*)d_in[0];
    const float* k   = (const float*)d_in[1];
    const float* v   = (const float*)d_in[2];
    const float* iw  = (const float*)d_in[3];
    const float* ib  = (const float*)d_in[4];
    const float* fw  = (const float*)d_in[5];
    const float* fb  = (const float*)d_in[6];
    const float* rms = (const float*)d_in[7];
    float* out = (float*)d_out;

    const int gates_smem = 8 * E3 * (int)sizeof(float);   // 96 KB
    const int attn_smem  = FREG_BYTES + 512 * 4;          // 180224 B
    cudaFuncSetAttribute(gates_kernel,
                         cudaFuncAttributeMaxDynamicSharedMemorySize, gates_smem);
    cudaFuncSetAttribute(attn_kernel,
                         cudaFuncAttributeMaxDynamicSharedMemorySize, attn_smem);

    gates_kernel<<<Bb * Sq / 32, 256, gates_smem>>>(q, k, v, iw, ib, fw, fb);
    scan_kernel<<<BHh, 1024>>>();
    attn_kernel<<<(Sq / (2 * TM)) * BHh, 256, attn_smem>>>(rms, out);
}

// round 12
// speedup vs baseline: 6.4857x; 1.1628x over previous
#include <cuda_runtime.h>
#include <cuda_fp16.h>
#include <math.h>
#include <stdint.h>

#define Sq 2048
#define Ed 1024
#define NHh 4
#define HDd 256
#define Bb 2
#define BHh 8
#define E3 3072

#define TM 64
#define TN 64
#define LDH 264      // half stride for Q/K/V tiles (528B: mod128=16 -> ldmatrix conflict-free)
#define PLD 72       // half stride for P tile

#define FULLMASK 0xffffffffu

// ---------------- device-global scratch ----------------
__device__ float g_ig[BHh * Sq];
__device__ float g_fg[BHh * Sq];
__device__ float g_a[BHh * Sq];
__device__ float g_pm[BHh * Sq];
__device__ float g_m[BHh * Sq];
__device__ float g_ta[BHh * (Sq / TN)];
__device__ __half g_qh[(size_t)BHh * Sq * HDd];   // [b][h][s][d]
__device__ __half g_kh[(size_t)BHh * Sq * HDd];   // [b][h][s][d]
__device__ __half g_vh[(size_t)BHh * Sq * HDd];   // [b][h][s][d]

struct alignas(8) H4 { __half2 a, b; };

// ---------------- PTX helpers ----------------
__device__ __forceinline__ void mma16(float d[4], uint32_t a0, uint32_t a1,
                                      uint32_t a2, uint32_t a3,
                                      uint32_t b0, uint32_t b1) {
    asm volatile(
        "mma.sync.aligned.m16n8k16.row.col.f32.f16.f16.f32 "
        "{%0,%1,%2,%3}, {%4,%5,%6,%7}, {%8,%9}, {%0,%1,%2,%3};\n"
        : "+f"(d[0]), "+f"(d[1]), "+f"(d[2]), "+f"(d[3])
        : "r"(a0), "r"(a1), "r"(a2), "r"(a3), "r"(b0), "r"(b1));
}

__device__ __forceinline__ void ldsm4(uint32_t& r0, uint32_t& r1, uint32_t& r2,
                                      uint32_t& r3, uint32_t addr) {
    asm volatile("ldmatrix.sync.aligned.m8n8.x4.shared.b16 {%0,%1,%2,%3}, [%4];\n"
                 : "=r"(r0), "=r"(r1), "=r"(r2), "=r"(r3) : "r"(addr));
}

__device__ __forceinline__ void ldsm4t(uint32_t& r0, uint32_t& r1, uint32_t& r2,
                                       uint32_t& r3, uint32_t addr) {
    asm volatile("ldmatrix.sync.aligned.m8n8.x4.trans.shared.b16 {%0,%1,%2,%3}, [%4];\n"
                 : "=r"(r0), "=r"(r1), "=r"(r2), "=r"(r3) : "r"(addr));
}

__device__ __forceinline__ void cpa16(uint32_t dst, const void* src) {
    asm volatile("cp.async.cg.shared.global [%0], [%1], 16;\n" :: "r"(dst), "l"(src));
}
#define CP_COMMIT() asm volatile("cp.async.commit_group;\n")
#define CP_WAIT(n)  asm volatile("cp.async.wait_group %0;\n" :: "n"(n))

// ---------------------------------------------------------------------------
// Kernel 1: gates + fp16 conversion of q,k,v into per-head layout.
// 512 blocks x 256 thr; one row per warp. Per section, all 8 float4 X loads
// are register-batched (MLP=8/warp) before the W-LDS/FFMA pass.
// ---------------------------------------------------------------------------
__global__ void __launch_bounds__(256)
gates_kernel(const float* __restrict__ q, const float* __restrict__ k,
             const float* __restrict__ v, const float* __restrict__ iw,
             const float* __restrict__ ib, const float* __restrict__ fw,
             const float* __restrict__ fb) {
    extern __shared__ float sWT[];   // [8][3072] = 96 KB, transposed W
    int t = threadIdx.x;
    int lane = t & 31, warp = t >> 5;

    // stage W transposed (conflict-free STS: word = r mod 32 distinct per lane)
    for (int r = t; r < E3; r += 256) {
        float4 wi = *(const float4*)(iw + (size_t)r * 4);
        float4 wf = *(const float4*)(fw + (size_t)r * 4);
        sWT[0 * E3 + r] = wi.x; sWT[1 * E3 + r] = wi.y;
        sWT[2 * E3 + r] = wi.z; sWT[3 * E3 + r] = wi.w;
        sWT[4 * E3 + r] = wf.x; sWT[5 * E3 + r] = wf.y;
        sWT[6 * E3 + r] = wf.z; sWT[7 * E3 + r] = wf.w;
    }
    __syncthreads();

    int bs = blockIdx.x * 8 + warp;
    int b = bs >> 11, s = bs & (Sq - 1);
    const float* qrow = q + (size_t)bs * Ed;
    const float* krow = k + (size_t)bs * Ed;
    const float* vrow = v + (size_t)bs * Ed;

    float acc[8];
    #pragma unroll
    for (int j = 0; j < 8; j++) acc[j] = 0.f;

    #pragma unroll 1
    for (int sec = 0; sec < 3; sec++) {
        const float* src = (sec == 0) ? qrow : (sec == 1) ? krow : vrow;
        __half* dst = (sec == 0) ? g_qh : (sec == 1) ? g_kh : g_vh;

        // batch all 8 X loads for this section (independent -> MLP=8)
        float4 xr[8];
        #pragma unroll
        for (int c = 0; c < 8; c++)
            xr[c] = *(const float4*)(src + (size_t)(lane + 32 * c) * 4);

        #pragma unroll
        for (int c = 0; c < 8; c++) {
            int fs = lane + 32 * c;          // float4 idx within section
            int rg = sec * Ed + fs * 4;      // W row of xr[c].x
            float4 x = xr[c];
            #pragma unroll
            for (int j = 0; j < 8; j++) {
                float4 wj = *(const float4*)(sWT + j * E3 + rg);
                acc[j] += x.x * wj.x + x.y * wj.y + x.z * wj.z + x.w * wj.w;
            }
            // fp16 conversion, coalesced 8B store
            int rf = fs * 4;                 // 0..1023 within section
            int head = rf >> 8, d = rf & 255;
            size_t off = ((size_t)(b * NHh + head) * Sq + s) * HDd + d;
            H4 hx;
            hx.a = __floats2half2_rn(x.x, x.y);
            hx.b = __floats2half2_rn(x.z, x.w);
            *(H4*)(dst + off) = hx;
        }
    }

    #pragma unroll
    for (int off = 16; off; off >>= 1)
        #pragma unroll
        for (int j = 0; j < 8; j++)
            acc[j] += __shfl_xor_sync(FULLMASK, acc[j], off);
    if (lane == 0) {
        #pragma unroll
        for (int h = 0; h < NHh; h++) {
            int idx = (b * NHh + h) * Sq + s;
            g_ig[idx] = acc[h] + ib[h];
            g_fg[idx] = acc[4 + h] + fb[h];
        }
    }
}

// ---------------------------------------------------------------------------
// Kernel 2: per-head scans + per-tile max of a[].
// ---------------------------------------------------------------------------
__global__ void scan_kernel() {
    __shared__ float sv[Sq];
    __shared__ float av[Sq];
    __shared__ float part[1024];
    int bh = blockIdx.x;
    int t = threadIdx.x;
    const float* fgp = g_fg + bh * Sq;
    const float* igp = g_ig + bh * Sq;

    for (int e = t; e < Sq; e += 1024) {
        float x = fgp[e];
        sv[e] = (x >= 0.f) ? -log1pf(expf(-x)) : (x - log1pf(expf(x)));
    }
    __syncthreads();

    float p = sv[2 * t] + sv[2 * t + 1];
    part[t] = p;
    __syncthreads();
    for (int off = 1; off < 1024; off <<= 1) {
        float x = (t >= off) ? part[t - off] : 0.f;
        __syncthreads();
        part[t] += x;
        __syncthreads();
    }
    float base = (t > 0) ? part[t - 1] : 0.f;
    float cs0 = base + sv[2 * t];
    float cs1 = cs0 + sv[2 * t + 1];
    av[2 * t]     = igp[2 * t]     - cs0;
    av[2 * t + 1] = igp[2 * t + 1] - cs1;
    __syncthreads();

    if (t < Sq / TN) {
        float mx = -3.4e38f;
        #pragma unroll 8
        for (int e = 0; e < TN; e++) mx = fmaxf(mx, av[t * TN + e]);
        g_ta[bh * (Sq / TN) + t] = mx;
    }

    part[t] = fmaxf(av[2 * t], av[2 * t + 1]);
    __syncthreads();
    for (int off = 1; off < 1024; off <<= 1) {
        float x = (t >= off) ? part[t - off] : -3.4e38f;
        __syncthreads();
        part[t] = fmaxf(part[t], x);
        __syncthreads();
    }
    float mbase = (t > 0) ? part[t - 1] : -3.4e38f;
    float pm0 = fmaxf(mbase, av[2 * t]);
    float pm1 = fmaxf(pm0, av[2 * t + 1]);

    int o = bh * Sq + 2 * t;
    g_a[o]      = av[2 * t];
    g_a[o + 1]  = av[2 * t + 1];
    g_pm[o]     = pm0;
    g_pm[o + 1] = pm1;
    g_m[o]      = cs0 + pm0;
    g_m[o + 1]  = cs1 + pm1;
}

// ---------------------------------------------------------------------------
// Kernel 3: fp16 attention, balanced pairing: 128 blocks (single wave),
// block (pr,bh) processes row tiles {31-pr, pr} -> exactly 33 col-iters each.
// V is [s][d]; PV B-fragments via ldmatrix.trans.
// ---------------------------------------------------------------------------
// smem map (halfs)
#define QS_OFF  0
#define TSZ     (TM * LDH)                 // 16896 halves per tile
#define KS_OFF  TSZ
#define VS_OFF  (KS_OFF + 2 * TSZ)
#define PS_OFF  (VS_OFF + 2 * TSZ)
#define HALF_TOT (PS_OFF + TM * PLD)       // 89088
#define FREG_BYTES (HALF_TOT * 2)          // 178176

__global__ void __launch_bounds__(256)
attn_kernel(const float* __restrict__ rms, float* __restrict__ out) {
    extern __shared__ __half smh[];
    float* fr    = (float*)((char*)smh + FREG_BYTES);
    float* npart = fr;          // 128
    float* pmr   = fr + 128;    // 64
    float* emr   = fr + 192;    // 64
    float* ejs   = fr + 256;    // 64
    float* rfac  = fr + 320;    // 64
    float* ssqp  = fr + 384;    // 128

    uint32_t smB = (uint32_t)__cvta_generic_to_shared(smh);

    int pr = blockIdx.x >> 3;             // 0..15
    int bh = blockIdx.x & 7;
    int b = bh >> 2, h = bh & 3;
    int t = threadIdx.x;
    int lane = t & 31, wid = t >> 5;
    int wr = wid & 3, wc = wid >> 2;
    int g = lane >> 2, c = lane & 3;
    const int iA = wr * 16 + g, iB = iA + 8;

    const __half* qh = g_qh + (size_t)bh * Sq * HDd;
    const __half* kh = g_kh + (size_t)bh * Sq * HDd;
    const __half* vh = g_vh + (size_t)bh * Sq * HDd;

    // per-lane ldmatrix patterns
    const int rowPat  = (lane & 7) + ((lane >> 3) & 1) * 8;   // A rows
    const int colPatA = (lane >> 4) * 8;                      // A cols
    const int rowPatB = (lane & 7) + ((lane >> 4) & 1) * 8;   // K-B rows (non-trans)
    const int colPatB = ((lane >> 3) & 1) * 8;                // K-B cols
    const int vRowL   = lane & 15;                            // V-B rows (trans)
    const int vColL   = wc * 128 + ((lane >> 4) & 1) * 8;     // V-B col base

    uint32_t aQaddr = smB + (uint32_t)(QS_OFF + (wr * 16 + rowPat) * LDH + colPatA) * 2;
    uint32_t aPaddr = smB + (uint32_t)(PS_OFF + (wr * 16 + rowPat) * PLD + colPatA) * 2;

    #pragma unroll 1
    for (int tile = 0; tile < 2; tile++) {
        int rt = tile ? pr : (Sq / TM - 1 - pr);   // heavy tile first
        int i0 = rt * TM;

        __syncthreads();   // smem safe to reinit (prev tile's readers done)

        // Q tile + K/V stage 0 (one cp.async group)
        for (int idx = t; idx < TM * 32; idx += 256) {
            int i = idx >> 5, ch = (idx & 31) << 3;
            cpa16(smB + (uint32_t)(QS_OFF + i * LDH + ch) * 2,
                  qh + (size_t)(i0 + i) * HDd + ch);
            cpa16(smB + (uint32_t)(KS_OFF + i * LDH + ch) * 2,
                  kh + (size_t)i * HDd + ch);
            cpa16(smB + (uint32_t)(VS_OFF + i * LDH + ch) * 2,
                  vh + (size_t)i * HDd + ch);
        }
        CP_COMMIT();

        if (t < 128) npart[t] = 0.f;
        if (t < TM) {
            pmr[t] = g_pm[bh * Sq + i0 + t];
            emr[t] = __expf(-g_m[bh * Sq + i0 + t]);
        }

        float accO[16][4];
        #pragma unroll
        for (int nt = 0; nt < 16; nt++)
            #pragma unroll
            for (int r = 0; r < 4; r++) accO[nt][r] = 0.f;

        #pragma unroll 1
        for (int jt = 0; jt <= rt; jt++) {
            int buf = jt & 1;
            int j0 = jt * TN;

            if (t < TM) {
                float ta = g_ta[bh * (Sq / TN) + jt];
                ejs[t]  = __expf(g_a[bh * Sq + j0 + t] - ta);
                rfac[t] = __expf(ta - pmr[t]);
            }

            CP_WAIT(0);
            __syncthreads();   // stage[buf] + ejs/rfac ready; prev readers done

            if (jt < rt) {     // prefetch next stage
                int nj0 = j0 + TN, nbuf = buf ^ 1;
                for (int idx = t; idx < TM * 32; idx += 256) {
                    int i = idx >> 5, ch = (idx & 31) << 3;
                    cpa16(smB + (uint32_t)(KS_OFF + nbuf * TSZ + i * LDH + ch) * 2,
                          kh + (size_t)(nj0 + i) * HDd + ch);
                    cpa16(smB + (uint32_t)(VS_OFF + nbuf * TSZ + i * LDH + ch) * 2,
                          vh + (size_t)(nj0 + i) * HDd + ch);
                }
                CP_COMMIT();
            }

            // ---- QK^T: rows [wr*16,+16) x cols [wc*32,+32) ----
            float acc[4][4];
            #pragma unroll
            for (int nt = 0; nt < 4; nt++)
                #pragma unroll
                for (int r = 0; r < 4; r++) acc[nt][r] = 0.f;

            uint32_t bK0 = smB + (uint32_t)(KS_OFF + buf * TSZ
                              + (wc * 32 + rowPatB) * LDH + colPatB) * 2;
            uint32_t bK1 = bK0 + 16 * LDH * 2;
            #pragma unroll
            for (int kk = 0; kk < HDd; kk += 16) {
                uint32_t a0, a1, a2, a3, b00, b01, b10, b11, b20, b21, b30, b31;
                ldsm4(a0, a1, a2, a3, aQaddr + kk * 2);
                ldsm4(b00, b01, b10, b11, bK0 + kk * 2);
                ldsm4(b20, b21, b30, b31, bK1 + kk * 2);
                mma16(acc[0], a0, a1, a2, a3, b00, b01);
                mma16(acc[1], a0, a1, a2, a3, b10, b11);
                mma16(acc[2], a0, a1, a2, a3, b20, b21);
                mma16(acc[3], a0, a1, a2, a3, b30, b31);
            }

            // ---- scale, mask, store P (half), row sums ----
            bool diag = (jt == rt);
            float rA = rfac[iA] * 0.0625f;
            float rB = rfac[iB] * 0.0625f;
            float s0 = 0.f, s1 = 0.f;
            __half* Ps = smh + PS_OFF;
            #pragma unroll
            for (int nt = 0; nt < 4; nt++) {
                int j = wc * 32 + nt * 8 + 2 * c;
                float e0 = ejs[j], e1 = ejs[j + 1];
                float p00 = acc[nt][0] * rA * e0;
                float p01 = acc[nt][1] * rA * e1;
                float p10 = acc[nt][2] * rB * e0;
                float p11 = acc[nt][3] * rB * e1;
                if (diag) {
                    if (j > iA)     p00 = 0.f;
                    if (j + 1 > iA) p01 = 0.f;
                    if (j > iB)     p10 = 0.f;
                    if (j + 1 > iB) p11 = 0.f;
                }
                *(__half2*)(Ps + iA * PLD + j) = __floats2half2_rn(p00, p01);
                *(__half2*)(Ps + iB * PLD + j) = __floats2half2_rn(p10, p11);
                s0 += p00 + p01;
                s1 += p10 + p11;
            }
            s0 += __shfl_xor_sync(FULLMASK, s0, 1);
            s0 += __shfl_xor_sync(FULLMASK, s0, 2);
            s1 += __shfl_xor_sync(FULLMASK, s1, 1);
            s1 += __shfl_xor_sync(FULLMASK, s1, 2);
            if (c == 0) {
                npart[wc * 64 + iA] += s0;
                npart[wc * 64 + iB] += s1;
            }

            __syncthreads();   // P visible

            // ---- O += P @ V : rows [wr*16,+16) x d-cols [wc*128,+128) ----
            uint32_t vB = smB + (uint32_t)(VS_OFF + buf * TSZ + vRowL * LDH + vColL) * 2;
            #pragma unroll
            for (int kk = 0; kk < TN; kk += 16) {
                uint32_t a0, a1, a2, a3;
                ldsm4(a0, a1, a2, a3, aPaddr + kk * 2);
                uint32_t vRow = vB + (uint32_t)(kk * LDH) * 2;
                #pragma unroll
                for (int nb = 0; nb < 8; nb++) {
                    uint32_t b0, b1, b2, b3;
                    ldsm4t(b0, b1, b2, b3, vRow + (uint32_t)(nb * 16) * 2);
                    mma16(accO[nb * 2],     a0, a1, a2, a3, b0, b1);
                    mma16(accO[nb * 2 + 1], a0, a1, a2, a3, b2, b3);
                }
            }
        }
        __syncthreads();

        // ---- epilogue: 1/(n+eps), RMSNorm over HD=256, write out ----
        float nA = fmaxf(npart[iA] + npart[64 + iA], emr[iA]) + 1e-6f;
        float nB = fmaxf(npart[iB] + npart[64 + iB], emr[iB]) + 1e-6f;
        float invA = 1.f / nA, invB = 1.f / nB;
        float ssqA = 0.f, ssqB = 0.f;
        #pragma unroll
        for (int nt = 0; nt < 16; nt++) {
            accO[nt][0] *= invA; accO[nt][1] *= invA;
            accO[nt][2] *= invB; accO[nt][3] *= invB;
            ssqA += accO[nt][0] * accO[nt][0] + accO[nt][1] * accO[nt][1];
            ssqB += accO[nt][2] * accO[nt][2] + accO[nt][3] * accO[nt][3];
        }
        ssqA += __shfl_xor_sync(FULLMASK, ssqA, 1);
        ssqA += __shfl_xor_sync(FULLMASK, ssqA, 2);
        ssqB += __shfl_xor_sync(FULLMASK, ssqB, 1);
        ssqB += __shfl_xor_sync(FULLMASK, ssqB, 2);
        if (c == 0) {
            ssqp[wc * 64 + iA] = ssqA;
            ssqp[wc * 64 + iB] = ssqB;
        }
        __syncthreads();
        float rstdA = rsqrtf((ssqp[iA] + ssqp[64 + iA]) * (1.f / 256.f) + 1e-6f);
        float rstdB = rsqrtf((ssqp[iB] + ssqp[64 + iB]) * (1.f / 256.f) + 1e-6f);

        float* ob = out + ((size_t)(b * Sq + i0)) * Ed + h * HDd;
        #pragma unroll
        for (int nt = 0; nt < 16; nt++) {
            int col = wc * 128 + nt * 8 + 2 * c;
            float rs0 = rms[col], rs1 = rms[col + 1];
            *(float2*)(ob + (size_t)iA * Ed + col) =
                make_float2(accO[nt][0] * rstdA * (1.f + rs0),
                            accO[nt][1] * rstdA * (1.f + rs1));
            *(float2*)(ob + (size_t)iB * Ed + col) =
                make_float2(accO[nt][2] * rstdB * (1.f + rs0),
                            accO[nt][3] * rstdB * (1.f + rs1));
        }
    }
}

// ---------------------------------------------------------------------------
extern "C" void kernel_launch(void* const* d_in, const int* in_sizes, int n_in,
                              void* d_out, int out_size) {
    (void)in_sizes; (void)n_in; (void)out_size;
    const float* q   = (const float*)d_in[0];
    const float* k   = (const float*)d_in[1];
    const float* v   = (const float*)d_in[2];
    const float* iw  = (const float*)d_in[3];
    const float* ib  = (const float*)d_in[4];
    const float* fw  = (const float*)d_in[5];
    const float* fb  = (const float*)d_in[6];
    const float* rms = (const float*)d_in[7];
    float* out = (float*)d_out;

    const int gates_smem = 8 * E3 * (int)sizeof(float);   // 96 KB
    const int attn_smem  = FREG_BYTES + 512 * 4;          // 180224 B
    cudaFuncSetAttribute(gates_kernel,
                         cudaFuncAttributeMaxDynamicSharedMemorySize, gates_smem);
    cudaFuncSetAttribute(attn_kernel,
                         cudaFuncAttributeMaxDynamicSharedMemorySize, attn_smem);

    gates_kernel<<<Bb * Sq / 8, 256, gates_smem>>>(q, k, v, iw, ib, fw, fb);
    scan_kernel<<<BHh, 1024>>>();
    attn_kernel<<<(Sq / (2 * TM)) * BHh, 256, attn_smem>>>(rms, out);
}